// round 3
// baseline (speedup 1.0000x reference)
#include <cuda_runtime.h>

#define D 128
#define MAX_NODES 100096

// Scratch (no allocation allowed — __device__ globals).
__device__ __align__(16) float g_agg[(size_t)MAX_NODES * D];   // 51.2 MB
__device__ int g_outdeg[MAX_NODES];
__device__ int g_indeg[MAX_NODES];

// ---------------------------------------------------------------------------
// Kernel 1: zero agg + degree arrays
// ---------------------------------------------------------------------------
__global__ void zero_kernel(int n_nodes) {
    size_t i = (size_t)blockIdx.x * blockDim.x + threadIdx.x;
    size_t stride = (size_t)gridDim.x * blockDim.x;
    size_t total4 = (size_t)n_nodes * (D / 4);
    float4 z = make_float4(0.f, 0.f, 0.f, 0.f);
    for (size_t idx = i; idx < total4; idx += stride)
        reinterpret_cast<float4*>(g_agg)[idx] = z;
    for (size_t idx = i; idx < (size_t)n_nodes; idx += stride) {
        g_outdeg[idx] = 0;
        g_indeg[idx]  = 0;
    }
}

// ---------------------------------------------------------------------------
// Kernel 2: degree counts (int32 indices!)
// ---------------------------------------------------------------------------
__global__ void degree_kernel(const int* __restrict__ src,
                              const int* __restrict__ dst,
                              int n_edges, int n_nodes) {
    int i = blockIdx.x * blockDim.x + threadIdx.x;
    int stride = gridDim.x * blockDim.x;
    for (int e = i; e < n_edges; e += stride) {
        unsigned s = (unsigned)src[e];
        unsigned d = (unsigned)dst[e];
        if (s < (unsigned)n_nodes) atomicAdd(&g_outdeg[s], 1);
        if (d < (unsigned)n_nodes) atomicAdd(&g_indeg[d], 1);
    }
}

// ---------------------------------------------------------------------------
// Kernel 3: edge scatter — one warp per edge.
// Lane l handles 4 contiguous floats: coalesced 512B gather from feat[src],
// scaled by out_deg^-1/2, scattered with red.global.add.v4.f32
// (4x fewer L2 atomic ops than scalar atomicAdd).
// ---------------------------------------------------------------------------
__global__ void scatter_kernel(const float* __restrict__ feat,
                               const int* __restrict__ src,
                               const int* __restrict__ dst,
                               int n_edges, int n_nodes) {
    int gtid = blockIdx.x * blockDim.x + threadIdx.x;
    int warp = gtid >> 5;
    int lane = gtid & 31;
    if (warp >= n_edges) return;

    unsigned s = (unsigned)src[warp];
    unsigned d = (unsigned)dst[warp];
    if (s >= (unsigned)n_nodes || d >= (unsigned)n_nodes) return;

    int od = g_outdeg[s];
    float scale = rsqrtf((float)(od > 0 ? od : 1));

    float4 v = reinterpret_cast<const float4*>(feat + (size_t)s * D)[lane];
    v.x *= scale; v.y *= scale; v.z *= scale; v.w *= scale;

    float* a = g_agg + (size_t)d * D + lane * 4;
    asm volatile("red.global.add.v4.f32 [%0], {%1, %2, %3, %4};"
                 :: "l"(a), "f"(v.x), "f"(v.y), "f"(v.z), "f"(v.w)
                 : "memory");
}

// ---------------------------------------------------------------------------
// Kernel 4: rst = agg @ W, scaled by in_deg^-1/2.
// Block: 128 threads computes a 32-row x 64-col tile (grid.y selects col half).
// Smem: W half [128][64] = 32KB, A tile transposed [128][32] = 16KB.
// ---------------------------------------------------------------------------
__global__ void gemm_kernel(const float* __restrict__ weight,
                            float* __restrict__ out,
                            int n_nodes) {
    __shared__ __align__(16) float Wsh[D][64];    // [k][c]
    __shared__ __align__(16) float Ash[D][32];    // [k][r] (transposed)

    int tid  = threadIdx.x;          // 0..127
    int row0 = blockIdx.x * 32;
    int col0 = blockIdx.y * 64;

    for (int idx = tid; idx < D * 16; idx += 128) {
        int k  = idx >> 4;
        int c4 = idx & 15;
        float4 w = *reinterpret_cast<const float4*>(&weight[k * D + col0 + c4 * 4]);
        *reinterpret_cast<float4*>(&Wsh[k][c4 * 4]) = w;
    }

    for (int idx = tid; idx < 32 * 32; idx += 128) {
        int k4 = idx >> 5;
        int r  = idx & 31;
        int row = row0 + r;
        float4 a = (row < n_nodes)
            ? *reinterpret_cast<const float4*>(&g_agg[(size_t)row * D + k4 * 4])
            : make_float4(0.f, 0.f, 0.f, 0.f);
        Ash[k4 * 4 + 0][r] = a.x;
        Ash[k4 * 4 + 1][r] = a.y;
        Ash[k4 * 4 + 2][r] = a.z;
        Ash[k4 * 4 + 3][r] = a.w;
    }
    __syncthreads();

    int cg = tid & 15;   // col group: 4 cols
    int rg = tid >> 4;   // row group: 4 rows

    float acc[4][4];
    #pragma unroll
    for (int i = 0; i < 4; i++)
        #pragma unroll
        for (int j = 0; j < 4; j++) acc[i][j] = 0.f;

    #pragma unroll 8
    for (int k = 0; k < D; k++) {
        float4 w = *reinterpret_cast<float4*>(&Wsh[k][cg * 4]);
        float4 a = *reinterpret_cast<float4*>(&Ash[k][rg * 4]);
        acc[0][0] += a.x * w.x; acc[0][1] += a.x * w.y; acc[0][2] += a.x * w.z; acc[0][3] += a.x * w.w;
        acc[1][0] += a.y * w.x; acc[1][1] += a.y * w.y; acc[1][2] += a.y * w.z; acc[1][3] += a.y * w.w;
        acc[2][0] += a.z * w.x; acc[2][1] += a.z * w.y; acc[2][2] += a.z * w.z; acc[2][3] += a.z * w.w;
        acc[3][0] += a.w * w.x; acc[3][1] += a.w * w.y; acc[3][2] += a.w * w.z; acc[3][3] += a.w * w.w;
    }

    #pragma unroll
    for (int i = 0; i < 4; i++) {
        int row = row0 + rg * 4 + i;
        if (row < n_nodes) {
            int id = g_indeg[row];
            float s = rsqrtf((float)(id > 0 ? id : 1));
            float4 o = make_float4(acc[i][0] * s, acc[i][1] * s, acc[i][2] * s, acc[i][3] * s);
            *reinterpret_cast<float4*>(&out[(size_t)row * D + col0 + cg * 4]) = o;
        }
    }
}

// ---------------------------------------------------------------------------
extern "C" void kernel_launch(void* const* d_in, const int* in_sizes, int n_in,
                              void* d_out, int out_size) {
    // Size-based input detection (robust to metadata ordering):
    //   weight: 128*128 = 16384 elements
    //   feat:   largest array (n_nodes * 128)
    //   src/dst: the remaining two equal-sized index arrays, in appearance order
    int i_feat = -1, i_w = -1, i_idx0 = -1, i_idx1 = -1;
    for (int i = 0; i < n_in; i++) {
        if (in_sizes[i] == D * D && i_w < 0) { i_w = i; continue; }
        if (i_feat < 0 || in_sizes[i] > in_sizes[i_feat]) {
            // largest so far becomes feat; previous feat candidate demotes to idx
            if (i_feat >= 0) { if (i_idx0 < 0) i_idx0 = i_feat; else i_idx1 = i_feat; }
            i_feat = i;
        } else {
            if (i_idx0 < 0) i_idx0 = i; else i_idx1 = i;
        }
    }
    // Fallback to positional if detection failed
    if (i_feat < 0 || i_w < 0 || i_idx0 < 0 || i_idx1 < 0) {
        i_feat = 0; i_w = 1; i_idx0 = 2; i_idx1 = 3;
    }

    const float* feat   = (const float*)d_in[i_feat];
    const float* weight = (const float*)d_in[i_w];
    const int*   src    = (const int*)d_in[i_idx0];   // int32 (JAX x64 disabled)
    const int*   dst    = (const int*)d_in[i_idx1];
    float* out = (float*)d_out;

    int n_nodes = in_sizes[i_feat] / D;
    int n_edges = in_sizes[i_idx0];

    zero_kernel<<<2048, 256>>>(n_nodes);
    degree_kernel<<<(n_edges + 255) / 256, 256>>>(src, dst, n_edges, n_nodes);

    long long threads = (long long)n_edges * 32;
    int blocks = (int)((threads + 255) / 256);
    scatter_kernel<<<blocks, 256>>>(feat, src, dst, n_edges, n_nodes);

    dim3 grid((n_nodes + 31) / 32, 2);
    gemm_kernel<<<grid, 128>>>(weight, out, n_nodes);
}

// round 4
// speedup vs baseline: 1.7303x; 1.7303x over previous
#include <cuda_runtime.h>

#define D 128
#define MAX_NODES 100096
#define DEG_CAP 64

// ---------------------------------------------------------------------------
// Scratch (__device__ globals; no allocation allowed)
// ---------------------------------------------------------------------------
__device__ __align__(16) float g_agg[(size_t)MAX_NODES * D];       // 51.2 MB
__device__ int   g_col[(size_t)MAX_NODES * DEG_CAP];               // 25.6 MB CSR-ish buckets
__device__ int   g_outdeg[MAX_NODES];
__device__ int   g_indeg[MAX_NODES];
__device__ int   g_cursor[MAX_NODES];
__device__ float g_rs[MAX_NODES];    // rsqrt(max(outdeg,1))
__device__ float g_ris[MAX_NODES];   // rsqrt(max(indeg,1))

// ---------------------------------------------------------------------------
// K1: zero degree/cursor arrays (g_agg does NOT need zeroing: aggregate
// kernel writes every row unconditionally)
// ---------------------------------------------------------------------------
__global__ void init_kernel(int n_nodes) {
    int i = blockIdx.x * blockDim.x + threadIdx.x;
    if (i < n_nodes) {
        g_outdeg[i] = 0;
        g_indeg[i]  = 0;
        g_cursor[i] = 0;
    }
}

// ---------------------------------------------------------------------------
// K2: degree histograms (int REDs)
// ---------------------------------------------------------------------------
__global__ void degree_kernel(const int* __restrict__ src,
                              const int* __restrict__ dst,
                              int n_edges, int n_nodes) {
    int e = blockIdx.x * blockDim.x + threadIdx.x;
    if (e >= n_edges) return;
    unsigned s = (unsigned)src[e];
    unsigned d = (unsigned)dst[e];
    if (s < (unsigned)n_nodes) atomicAdd(&g_outdeg[s], 1);
    if (d < (unsigned)n_nodes) atomicAdd(&g_indeg[d], 1);
}

// ---------------------------------------------------------------------------
// K3: precompute normalization scales
// ---------------------------------------------------------------------------
__global__ void scale_kernel(int n_nodes) {
    int i = blockIdx.x * blockDim.x + threadIdx.x;
    if (i < n_nodes) {
        int od = g_outdeg[i], id = g_indeg[i];
        g_rs[i]  = rsqrtf((float)(od > 0 ? od : 1));
        g_ris[i] = rsqrtf((float)(id > 0 ? id : 1));
    }
}

// ---------------------------------------------------------------------------
// K4: bucket fill — int atomics only (no float atomics anywhere)
// ---------------------------------------------------------------------------
__global__ void fill_kernel(const int* __restrict__ src,
                            const int* __restrict__ dst,
                            int n_edges, int n_nodes) {
    int e = blockIdx.x * blockDim.x + threadIdx.x;
    if (e >= n_edges) return;
    unsigned s = (unsigned)src[e];
    unsigned d = (unsigned)dst[e];
    if (s >= (unsigned)n_nodes || d >= (unsigned)n_nodes) return;
    int pos = atomicAdd(&g_cursor[d], 1);
    if (pos < DEG_CAP)
        g_col[(size_t)d * DEG_CAP + pos] = (int)s;
}

// ---------------------------------------------------------------------------
// K5: aggregate — one warp per destination node, register accumulation.
// Lane l owns 4 contiguous floats (float4). Gathers are 512B coalesced rows
// from L2-resident feat. Unroll-by-2 for MLP.
// ---------------------------------------------------------------------------
__global__ void aggregate_kernel(const float* __restrict__ feat, int n_nodes) {
    int warp = (blockIdx.x * blockDim.x + threadIdx.x) >> 5;
    int lane = threadIdx.x & 31;
    if (warp >= n_nodes) return;
    int d = warp;

    int deg = g_indeg[d];
    if (deg > DEG_CAP) deg = DEG_CAP;
    const int* cols = g_col + (size_t)d * DEG_CAP;
    const float4* feat4 = reinterpret_cast<const float4*>(feat);

    float4 acc = make_float4(0.f, 0.f, 0.f, 0.f);
    int i = 0;
    for (; i + 1 < deg; i += 2) {
        int s0 = cols[i];
        int s1 = cols[i + 1];
        float r0 = g_rs[s0];
        float r1 = g_rs[s1];
        float4 v0 = feat4[(size_t)s0 * 32 + lane];
        float4 v1 = feat4[(size_t)s1 * 32 + lane];
        acc.x += v0.x * r0 + v1.x * r1;
        acc.y += v0.y * r0 + v1.y * r1;
        acc.z += v0.z * r0 + v1.z * r1;
        acc.w += v0.w * r0 + v1.w * r1;
    }
    if (i < deg) {
        int s0 = cols[i];
        float r0 = g_rs[s0];
        float4 v0 = feat4[(size_t)s0 * 32 + lane];
        acc.x += v0.x * r0; acc.y += v0.y * r0;
        acc.z += v0.z * r0; acc.w += v0.w * r0;
    }
    reinterpret_cast<float4*>(g_agg)[(size_t)d * 32 + lane] = acc;
}

// ---------------------------------------------------------------------------
// K6: GEMM out = agg @ W (scaled by in_deg^-1/2).
// Block 256 thr, tile 64 rows x 128 cols, per-thread acc[8][4].
// Smem (dynamic 96KB): Wsh[128][128] (direct copy, k-major) + Ash[128][64]
// (transposed A tile). Mainloop per k: W = 32 contiguous float4 (conflict-
// free), A = 2 broadcast LDS.128 -> 6 crossbar cyc vs 32 FFMA => FFMA-bound.
// ---------------------------------------------------------------------------
__global__ void gemm_kernel(const float* __restrict__ weight,
                            float* __restrict__ out,
                            int n_nodes) {
    extern __shared__ __align__(16) float smem[];
    float* Wsh = smem;           // [128][128]
    float* Ash = smem + D * D;   // [128][64]  (Ash[k][r])

    int tid  = threadIdx.x;      // 0..255
    int row0 = blockIdx.x * 64;

    // Load W: identical layout (row-major [k][c] == k-major) -> straight copy
    {
        const float4* W4 = reinterpret_cast<const float4*>(weight);
        float4* Wsh4 = reinterpret_cast<float4*>(Wsh);
        #pragma unroll
        for (int i = 0; i < 16; i++)
            Wsh4[tid + i * 256] = W4[tid + i * 256];
    }

    // Load A tile transposed: idx -> (k4 = idx>>6, r = idx&63).
    // Warp: consecutive r, same k4 -> conflict-free STS; LDG is 32 scattered
    // 16B reads (L2-resident, acceptable).
    for (int idx = tid; idx < 32 * 64; idx += 256) {
        int k4 = idx >> 6;
        int r  = idx & 63;
        int row = row0 + r;
        float4 a = (row < n_nodes)
            ? reinterpret_cast<const float4*>(g_agg)[(size_t)row * 32 + k4]
            : make_float4(0.f, 0.f, 0.f, 0.f);
        Ash[(k4 * 4 + 0) * 64 + r] = a.x;
        Ash[(k4 * 4 + 1) * 64 + r] = a.y;
        Ash[(k4 * 4 + 2) * 64 + r] = a.z;
        Ash[(k4 * 4 + 3) * 64 + r] = a.w;
    }
    __syncthreads();

    int cg = tid & 31;   // 32 col-groups x 4 cols = 128 cols
    int rg = tid >> 5;   // 8 row-groups x 8 rows = 64 rows

    float acc[8][4];
    #pragma unroll
    for (int i = 0; i < 8; i++)
        #pragma unroll
        for (int j = 0; j < 4; j++) acc[i][j] = 0.f;

    #pragma unroll 8
    for (int k = 0; k < D; k++) {
        float4 w  = *reinterpret_cast<float4*>(&Wsh[k * D + cg * 4]);
        float4 a0 = *reinterpret_cast<float4*>(&Ash[k * 64 + rg * 8]);
        float4 a1 = *reinterpret_cast<float4*>(&Ash[k * 64 + rg * 8 + 4]);
        acc[0][0] += a0.x * w.x; acc[0][1] += a0.x * w.y; acc[0][2] += a0.x * w.z; acc[0][3] += a0.x * w.w;
        acc[1][0] += a0.y * w.x; acc[1][1] += a0.y * w.y; acc[1][2] += a0.y * w.z; acc[1][3] += a0.y * w.w;
        acc[2][0] += a0.z * w.x; acc[2][1] += a0.z * w.y; acc[2][2] += a0.z * w.z; acc[2][3] += a0.z * w.w;
        acc[3][0] += a0.w * w.x; acc[3][1] += a0.w * w.y; acc[3][2] += a0.w * w.z; acc[3][3] += a0.w * w.w;
        acc[4][0] += a1.x * w.x; acc[4][1] += a1.x * w.y; acc[4][2] += a1.x * w.z; acc[4][3] += a1.x * w.w;
        acc[5][0] += a1.y * w.x; acc[5][1] += a1.y * w.y; acc[5][2] += a1.y * w.z; acc[5][3] += a1.y * w.w;
        acc[6][0] += a1.z * w.x; acc[6][1] += a1.z * w.y; acc[6][2] += a1.z * w.z; acc[6][3] += a1.z * w.w;
        acc[7][0] += a1.w * w.x; acc[7][1] += a1.w * w.y; acc[7][2] += a1.w * w.z; acc[7][3] += a1.w * w.w;
    }

    #pragma unroll
    for (int i = 0; i < 8; i++) {
        int row = row0 + rg * 8 + i;
        if (row < n_nodes) {
            float s = g_ris[row];
            float4 o = make_float4(acc[i][0] * s, acc[i][1] * s,
                                   acc[i][2] * s, acc[i][3] * s);
            *reinterpret_cast<float4*>(&out[(size_t)row * D + cg * 4]) = o;
        }
    }
}

// ---------------------------------------------------------------------------
extern "C" void kernel_launch(void* const* d_in, const int* in_sizes, int n_in,
                              void* d_out, int out_size) {
    // Size-based input detection: weight == 128*128; feat is the largest;
    // the remaining two (in order) are src, dst.
    int i_feat = -1, i_w = -1, i_idx0 = -1, i_idx1 = -1;
    for (int i = 0; i < n_in; i++) {
        if (in_sizes[i] == D * D && i_w < 0) { i_w = i; continue; }
        if (i_feat < 0 || in_sizes[i] > in_sizes[i_feat]) {
            if (i_feat >= 0) { if (i_idx0 < 0) i_idx0 = i_feat; else i_idx1 = i_feat; }
            i_feat = i;
        } else {
            if (i_idx0 < 0) i_idx0 = i; else i_idx1 = i;
        }
    }
    if (i_feat < 0 || i_w < 0 || i_idx0 < 0 || i_idx1 < 0) {
        i_feat = 0; i_w = 1; i_idx0 = 2; i_idx1 = 3;
    }

    const float* feat   = (const float*)d_in[i_feat];
    const float* weight = (const float*)d_in[i_w];
    const int*   src    = (const int*)d_in[i_idx0];   // int32 (JAX x64 disabled)
    const int*   dst    = (const int*)d_in[i_idx1];
    float* out = (float*)d_out;

    int n_nodes = in_sizes[i_feat] / D;
    int n_edges = in_sizes[i_idx0];

    int nb_nodes = (n_nodes + 255) / 256;
    int nb_edges = (n_edges + 255) / 256;

    init_kernel<<<nb_nodes, 256>>>(n_nodes);
    degree_kernel<<<nb_edges, 256>>>(src, dst, n_edges, n_nodes);
    scale_kernel<<<nb_nodes, 256>>>(n_nodes);
    fill_kernel<<<nb_edges, 256>>>(src, dst, n_edges, n_nodes);

    // one warp per node
    int nb_agg = (n_nodes * 32 + 255) / 256;
    aggregate_kernel<<<nb_agg, 256>>>(feat, n_nodes);

    // GEMM: 96KB dynamic smem
    static int smem_set = 0;
    int smem_bytes = (D * D + D * 64) * sizeof(float);  // 96KB
    if (!smem_set) {
        cudaFuncSetAttribute(gemm_kernel,
                             cudaFuncAttributeMaxDynamicSharedMemorySize,
                             smem_bytes);
        smem_set = 1;
    }
    gemm_kernel<<<(n_nodes + 63) / 64, 256, smem_bytes>>>(weight, out, n_nodes);
}